// round 10
// baseline (speedup 1.0000x reference)
#include <cuda_runtime.h>
#include <cstdint>

#define Nn 32000
#define Ee 512000
#define Fk 256
#define Hh 4
#define Dd 64
#define Cc 256          // Hh * Dd
#define NEG 0.2f

// ---------------- scratch (device globals: no allocation allowed) ----------
__device__ float g_ft[Nn * Cc];        // projected features [N, 256]
__device__ float g_esrc[Nn * Hh];      // per-node src logits
__device__ float g_edst[Nn * Hh];      // per-node dst logits
__device__ int   g_count[Nn];          // in-degree (zeroed by agg for next replay)
__device__ int   g_off[Nn];            // CSR offsets
__device__ int   g_cur[Nn];            // scatter cursors
__device__ int   g_srclist[Ee];        // src node per CSR slot
__device__ float g_dlist[Ee];          // dist per CSR slot
__device__ float g_vlist[Ee * Hh];     // esrc[src] per CSR slot (4 floats)

// ---------------- tf32 tensor-core GEMM: ft = feat @ W ---------------------
#define BM 128
#define BN 64
#define BK 32
#define PA 36   // A smem pitch (floats) -> conflict-free fragment reads
#define PB 72   // B smem pitch (floats) -> conflict-free fragment reads

__device__ __forceinline__ uint32_t f2tf(float f) {
    uint32_t o;
    asm("cvt.rna.tf32.f32 %0, %1;" : "=r"(o) : "f"(f));
    return o;
}

__device__ __forceinline__ void mma_tf32(float c[4],
                                         const uint32_t a[4],
                                         const uint32_t b[2]) {
    asm volatile(
        "mma.sync.aligned.m16n8k8.row.col.f32.tf32.tf32.f32 "
        "{%0,%1,%2,%3}, {%4,%5,%6,%7}, {%8,%9}, {%0,%1,%2,%3};"
        : "+f"(c[0]), "+f"(c[1]), "+f"(c[2]), "+f"(c[3])
        : "r"(a[0]), "r"(a[1]), "r"(a[2]), "r"(a[3]),
          "r"(b[0]), "r"(b[1]));
}

__global__ void gemm_tc_kernel(const float* __restrict__ A,
                               const float* __restrict__ B,
                               const float* __restrict__ wsrc,
                               const float* __restrict__ wdst) {
    __shared__ uint32_t As[BM * PA];
    __shared__ uint32_t Bs[BK * PB];
    __shared__ float s_ps[BM][2];
    __shared__ float s_pd[BM][2];

    const int tid  = threadIdx.x;
    const int lane = tid & 31;
    const int warp = tid >> 5;
    const int wm   = warp >> 1;
    const int wn   = warp & 1;
    const int row0 = blockIdx.x * BM;
    const int col0 = blockIdx.y * BN;
    const int hd   = blockIdx.y;

    float c[2][4][4];
    #pragma unroll
    for (int mt = 0; mt < 2; mt++)
        #pragma unroll
        for (int nt = 0; nt < 4; nt++)
            #pragma unroll
            for (int r = 0; r < 4; r++) c[mt][nt][r] = 0.f;

    const int ar = tid >> 3;
    const int ac = (tid & 7) * 4;
    const int br = tid >> 4;
    const int bc = (tid & 15) * 4;

    float4 pa[4], pb[2];
    #pragma unroll
    for (int p = 0; p < 4; p++)
        pa[p] = *reinterpret_cast<const float4*>(
            &A[(row0 + ar + p * 32) * Fk + ac]);
    #pragma unroll
    for (int p = 0; p < 2; p++)
        pb[p] = *reinterpret_cast<const float4*>(
            &B[(br + p * 16) * Cc + col0 + bc]);

    const int NTILES = Fk / BK;
    for (int t = 0; t < NTILES; t++) {
        #pragma unroll
        for (int p = 0; p < 4; p++) {
            uint32_t* d = &As[(ar + p * 32) * PA + ac];
            d[0] = f2tf(pa[p].x); d[1] = f2tf(pa[p].y);
            d[2] = f2tf(pa[p].z); d[3] = f2tf(pa[p].w);
        }
        #pragma unroll
        for (int p = 0; p < 2; p++) {
            uint32_t* d = &Bs[(br + p * 16) * PB + bc];
            d[0] = f2tf(pb[p].x); d[1] = f2tf(pb[p].y);
            d[2] = f2tf(pb[p].z); d[3] = f2tf(pb[p].w);
        }
        __syncthreads();

        if (t + 1 < NTILES) {
            int k0 = (t + 1) * BK;
            #pragma unroll
            for (int p = 0; p < 4; p++)
                pa[p] = *reinterpret_cast<const float4*>(
                    &A[(row0 + ar + p * 32) * Fk + k0 + ac]);
            #pragma unroll
            for (int p = 0; p < 2; p++)
                pb[p] = *reinterpret_cast<const float4*>(
                    &B[(k0 + br + p * 16) * Cc + col0 + bc]);
        }

        #pragma unroll
        for (int ks = 0; ks < 4; ks++) {
            const int kk = ks * 8;
            uint32_t af[2][4], bf[4][2];
            #pragma unroll
            for (int mt = 0; mt < 2; mt++) {
                int r = wm * 32 + mt * 16 + (lane >> 2);
                af[mt][0] = As[r * PA + kk + (lane & 3)];
                af[mt][1] = As[(r + 8) * PA + kk + (lane & 3)];
                af[mt][2] = As[r * PA + kk + (lane & 3) + 4];
                af[mt][3] = As[(r + 8) * PA + kk + (lane & 3) + 4];
            }
            #pragma unroll
            for (int nt = 0; nt < 4; nt++) {
                int nc = wn * 32 + nt * 8 + (lane >> 2);
                bf[nt][0] = Bs[(kk + (lane & 3)) * PB + nc];
                bf[nt][1] = Bs[(kk + (lane & 3) + 4) * PB + nc];
            }
            #pragma unroll
            for (int mt = 0; mt < 2; mt++)
                #pragma unroll
                for (int nt = 0; nt < 4; nt++)
                    mma_tf32(c[mt][nt], af[mt], bf[nt]);
        }
        __syncthreads();
    }

    // epilogue 1: write ft accumulators
    #pragma unroll
    for (int mt = 0; mt < 2; mt++) {
        #pragma unroll
        for (int nt = 0; nt < 4; nt++) {
            int r  = row0 + wm * 32 + mt * 16 + (lane >> 2);
            int cc = col0 + wn * 32 + nt * 8 + 2 * (lane & 3);
            *reinterpret_cast<float2*>(&g_ft[r * Cc + cc]) =
                make_float2(c[mt][nt][0], c[mt][nt][1]);
            *reinterpret_cast<float2*>(&g_ft[(r + 8) * Cc + cc]) =
                make_float2(c[mt][nt][2], c[mt][nt][3]);
        }
    }

    // epilogue 2: attention logits for head hd from register accumulators
    float2 ws2[4], wd2[4];
    #pragma unroll
    for (int nt = 0; nt < 4; nt++) {
        int cl = wn * 32 + nt * 8 + 2 * (lane & 3);
        ws2[nt] = *reinterpret_cast<const float2*>(&wsrc[hd * Dd + cl]);
        wd2[nt] = *reinterpret_cast<const float2*>(&wdst[hd * Dd + cl]);
    }
    #pragma unroll
    for (int mt = 0; mt < 2; mt++) {
        float ps0 = 0.f, pd0 = 0.f, ps1 = 0.f, pd1 = 0.f;
        #pragma unroll
        for (int nt = 0; nt < 4; nt++) {
            ps0 += c[mt][nt][0] * ws2[nt].x + c[mt][nt][1] * ws2[nt].y;
            pd0 += c[mt][nt][0] * wd2[nt].x + c[mt][nt][1] * wd2[nt].y;
            ps1 += c[mt][nt][2] * ws2[nt].x + c[mt][nt][3] * ws2[nt].y;
            pd1 += c[mt][nt][2] * wd2[nt].x + c[mt][nt][3] * wd2[nt].y;
        }
        #pragma unroll
        for (int m = 1; m < 4; m <<= 1) {
            ps0 += __shfl_xor_sync(0xffffffffu, ps0, m);
            pd0 += __shfl_xor_sync(0xffffffffu, pd0, m);
            ps1 += __shfl_xor_sync(0xffffffffu, ps1, m);
            pd1 += __shfl_xor_sync(0xffffffffu, pd1, m);
        }
        if ((lane & 3) == 0) {
            int r = wm * 32 + mt * 16 + (lane >> 2);
            s_ps[r][wn]     = ps0;  s_pd[r][wn]     = pd0;
            s_ps[r + 8][wn] = ps1;  s_pd[r + 8][wn] = pd1;
        }
    }
    __syncthreads();
    if (tid < BM) {
        g_esrc[(row0 + tid) * Hh + hd] = s_ps[tid][0] + s_ps[tid][1];
        g_edst[(row0 + tid) * Hh + hd] = s_pd[tid][0] + s_pd[tid][1];
    }
}

// ---------------- CSR build -------------------------------------------------
// 4 edges per thread (stride 256) -> 4 independent atomic chains in flight.
__global__ void hist_kernel(const int* __restrict__ dst) {
    int base = blockIdx.x * 1024 + threadIdx.x;
    int d0 = dst[base];
    int d1 = dst[base + 256];
    int d2 = dst[base + 512];
    int d3 = dst[base + 768];
    atomicAdd(&g_count[d0], 1);
    atomicAdd(&g_count[d1], 1);
    atomicAdd(&g_count[d2], 1);
    atomicAdd(&g_count[d3], 1);
}

// fused scan (125 blocks x 256): block b reduces g_count[0..b*256) for its
// global offset, then local exclusive scan of its 256 counts.
__global__ void scan_kernel() {
    __shared__ int ws[8];
    __shared__ int wo[8];
    __shared__ int s_boff;
    int b = blockIdx.x, t = threadIdx.x, lane = t & 31, w = t >> 5;

    {
        int p = 0;
        for (int i = t; i < b * 256; i += 256) p += g_count[i];
        #pragma unroll
        for (int d = 16; d > 0; d >>= 1) p += __shfl_xor_sync(0xffffffffu, p, d);
        if (lane == 0) ws[w] = p;
        __syncthreads();
        if (t == 0) {
            int s = 0;
            #pragma unroll
            for (int k = 0; k < 8; k++) s += ws[k];
            s_boff = s;
        }
        __syncthreads();
    }

    int i = b * 256 + t;
    int v = g_count[i];
    int x = v;
    #pragma unroll
    for (int d = 1; d < 32; d <<= 1) {
        int y = __shfl_up_sync(0xffffffffu, x, d);
        if (lane >= d) x += y;
    }
    if (lane == 31) ws[w] = x;
    __syncthreads();
    if (t == 0) {
        int a = 0;
        #pragma unroll
        for (int k = 0; k < 8; k++) { wo[k] = a; a += ws[k]; }
    }
    __syncthreads();
    int excl = x - v + wo[w] + s_boff;
    g_off[i] = excl;
    g_cur[i] = excl;
}

// scatter: assign CSR slots (4 edges/thread for MLP). No gemm dependence.
__global__ void scatter_kernel(const int* __restrict__ src,
                               const int* __restrict__ dst,
                               const float* __restrict__ dist) {
    int base = blockIdx.x * 1024 + threadIdx.x;
    #pragma unroll
    for (int k = 0; k < 4; k++) {
        int e = base + k * 256;
        int d = dst[e];
        int s = src[e];
        float di = dist[e];
        int p = atomicAdd(&g_cur[d], 1);
        g_srclist[p] = s;
        g_dlist[p]   = di;
    }
}

// vgather: vlist[p] = esrc[srclist[p]] (after gemm). 4 slots/thread.
__global__ void vgather_kernel() {
    int base = blockIdx.x * 1024 + threadIdx.x;
    int s0 = g_srclist[base];
    int s1 = g_srclist[base + 256];
    int s2 = g_srclist[base + 512];
    int s3 = g_srclist[base + 768];
    float4 e0 = *reinterpret_cast<const float4*>(&g_esrc[s0 * Hh]);
    float4 e1 = *reinterpret_cast<const float4*>(&g_esrc[s1 * Hh]);
    float4 e2 = *reinterpret_cast<const float4*>(&g_esrc[s2 * Hh]);
    float4 e3 = *reinterpret_cast<const float4*>(&g_esrc[s3 * Hh]);
    *reinterpret_cast<float4*>(&g_vlist[(base)       * Hh]) = e0;
    *reinterpret_cast<float4*>(&g_vlist[(base + 256) * Hh]) = e1;
    *reinterpret_cast<float4*>(&g_vlist[(base + 512) * Hh]) = e2;
    *reinterpret_cast<float4*>(&g_vlist[(base + 768) * Hh]) = e3;
}

// ---------------- softmax + aggregation ------------------------------------
__device__ __forceinline__ void msum(float& m, float& s, float m2, float s2) {
    float mn = fmaxf(m, m2);
    float a = (s  != 0.f) ? s  * __expf(m  - mn) : 0.f;
    float b = (s2 != 0.f) ? s2 * __expf(m2 - mn) : 0.f;
    m = mn; s = a + b;
}

#define ETILE 64

// one block per destination node, 256 threads = one output element each.
// also zeroes g_count[n] for the next graph replay.
__global__ void agg_kernel(float* __restrict__ out) {
    const int n    = blockIdx.x;
    const int tid  = threadIdx.x;
    const int lane = tid & 31;
    const int wrp  = tid >> 5;
    const int off  = g_off[n];
    const int deg  = g_count[n];

    __shared__ float s_max[Hh];
    __shared__ float s_rden[Hh];
    __shared__ float s_edst[Hh];
    __shared__ float s_wm[8][Hh];
    __shared__ float s_ws[8][Hh];
    __shared__ int   s_src[ETILE];
    __shared__ float s_a[ETILE][Hh];

    if (tid < Hh) s_edst[tid] = g_edst[n * Hh + tid];
    __syncthreads();

    const float NEGINF = __int_as_float(0xff800000);

    // single online-softmax pass — fully coalesced vlist reads
    {
        float lm[Hh] = {NEGINF, NEGINF, NEGINF, NEGINF};
        float ls[Hh] = {0.f, 0.f, 0.f, 0.f};
        for (int i = tid; i < deg; i += 256) {
            float4 es = *reinterpret_cast<const float4*>(&g_vlist[(off + i) * Hh]);
            float ev[Hh] = {es.x, es.y, es.z, es.w};
            #pragma unroll
            for (int h = 0; h < Hh; h++) {
                float v = ev[h] + s_edst[h];
                v = (v >= 0.f) ? v : NEG * v;
                float mn = fmaxf(lm[h], v);
                float a  = (ls[h] != 0.f) ? ls[h] * __expf(lm[h] - mn) : 0.f;
                ls[h] = a + __expf(v - mn);
                lm[h] = mn;
            }
        }
        #pragma unroll
        for (int d = 16; d > 0; d >>= 1) {
            #pragma unroll
            for (int h = 0; h < Hh; h++) {
                float m2 = __shfl_xor_sync(0xffffffffu, lm[h], d);
                float s2 = __shfl_xor_sync(0xffffffffu, ls[h], d);
                msum(lm[h], ls[h], m2, s2);
            }
        }
        if (lane == 0) {
            #pragma unroll
            for (int h = 0; h < Hh; h++) { s_wm[wrp][h] = lm[h]; s_ws[wrp][h] = ls[h]; }
        }
    }
    __syncthreads();
    if (wrp == 0) {
        int h = lane >> 3;
        int w = lane & 7;
        float m = s_wm[w][h];
        float s = s_ws[w][h];
        #pragma unroll
        for (int d = 1; d < 8; d <<= 1) {
            float m2 = __shfl_xor_sync(0xffffffffu, m, d);
            float s2 = __shfl_xor_sync(0xffffffffu, s, d);
            msum(m, s, m2, s2);
        }
        if (w == 0) {
            s_max[h]  = m;
            s_rden[h] = (s > 0.f) ? 1.f / s : 0.f;
        }
    }
    __syncthreads();

    // phase C: tiled weighted aggregation; coefficients coalesced from vlist
    const int h = tid >> 6;
    float acc = 0.f;

    for (int t0 = 0; t0 < deg; t0 += ETILE) {
        const int tl = min(ETILE, deg - t0);
        {
            int i  = tid >> 2;
            int hh = tid & 3;
            if (i < tl) {
                int p = off + t0 + i;
                if (hh == 0) s_src[i] = g_srclist[p];
                float v = g_vlist[p * Hh + hh] + s_edst[hh];
                v = (v >= 0.f) ? v : NEG * v;
                s_a[i][hh] = __expf(v - s_max[hh]) * s_rden[hh] * g_dlist[p];
            }
        }
        __syncthreads();

        int i = 0;
        for (; i + 4 <= tl; i += 4) {
            int   s0 = s_src[i],     s1 = s_src[i + 1];
            int   s2 = s_src[i + 2], s3 = s_src[i + 3];
            float f0 = g_ft[s0 * Cc + tid];
            float f1 = g_ft[s1 * Cc + tid];
            float f2 = g_ft[s2 * Cc + tid];
            float f3 = g_ft[s3 * Cc + tid];
            acc += f0 * s_a[i][h]     + f1 * s_a[i + 1][h]
                 + f2 * s_a[i + 2][h] + f3 * s_a[i + 3][h];
        }
        for (; i < tl; i++) {
            acc += g_ft[s_src[i] * Cc + tid] * s_a[i][h];
        }
        __syncthreads();
    }

    out[n * Cc + tid] = acc;

    // reset in-degree for next graph replay (hist accumulates)
    if (tid == 0) g_count[n] = 0;
}

// ---------------- launch ----------------------------------------------------
extern "C" void kernel_launch(void* const* d_in, const int* in_sizes, int n_in,
                              void* d_out, int out_size) {
    const float* feat = (const float*)d_in[0];
    const float* dist = (const float*)d_in[1];
    const float* W    = (const float*)d_in[2];
    const float* wsrc = (const float*)d_in[3];
    const float* wdst = (const float*)d_in[4];
    const int*   src  = (const int*)d_in[5];
    const int*   dst  = (const int*)d_in[6];
    float*       out  = (float*)d_out;

    (void)in_sizes; (void)n_in; (void)out_size;

    hist_kernel<<<Ee / 1024, 256>>>(dst);                                   // 0
    scan_kernel<<<125, 256>>>();                                            // 1
    scatter_kernel<<<Ee / 1024, 256>>>(src, dst, dist);                     // 2
    gemm_tc_kernel<<<dim3(Nn / BM, Cc / BN), 256>>>(feat, W, wsrc, wdst);   // 3 (profiled)
    vgather_kernel<<<Ee / 1024, 256>>>();                                   // 4
    agg_kernel<<<Nn, 256>>>(out);                                           // 5
}

// round 15
// speedup vs baseline: 1.9790x; 1.9790x over previous
#include <cuda_runtime.h>
#include <cstdint>

#define Nn 32000
#define Ee 512000
#define Fk 256
#define Hh 4
#define Dd 64
#define Cc 256          // Hh * Dd
#define NEG 0.2f

// ---------------- scratch (device globals: no allocation allowed) ----------
__device__ float g_ft[Nn * Cc];        // projected features [N, 256]
__device__ float g_esrc[Nn * Hh];      // per-node src logits
__device__ float g_edst[Nn * Hh];      // per-node dst logits
__device__ int   g_count[Nn];          // in-degree (zeroed by agg for next replay)
__device__ int   g_off[Nn];            // CSR offsets
__device__ int   g_cur[Nn];            // scatter cursors
__device__ int   g_srclist[Ee];        // src node per CSR slot
__device__ float g_dlist[Ee];          // dist per CSR slot
__device__ float g_vlist[Ee * Hh];     // esrc[src] per CSR slot (4 floats)

// ---------------- tf32 tensor-core GEMM: ft = feat @ W ---------------------
// (round-9 proven version: PA=36/PB=72 conflict-free LDS.32 fragments)
#define BM 128
#define BN 64
#define BK 32
#define PA 36
#define PB 72

__device__ __forceinline__ uint32_t f2tf(float f) {
    uint32_t o;
    asm("cvt.rna.tf32.f32 %0, %1;" : "=r"(o) : "f"(f));
    return o;
}

__device__ __forceinline__ void mma_tf32(float c[4],
                                         const uint32_t a[4],
                                         const uint32_t b[2]) {
    asm volatile(
        "mma.sync.aligned.m16n8k8.row.col.f32.tf32.tf32.f32 "
        "{%0,%1,%2,%3}, {%4,%5,%6,%7}, {%8,%9}, {%0,%1,%2,%3};"
        : "+f"(c[0]), "+f"(c[1]), "+f"(c[2]), "+f"(c[3])
        : "r"(a[0]), "r"(a[1]), "r"(a[2]), "r"(a[3]),
          "r"(b[0]), "r"(b[1]));
}

__global__ void gemm_tc_kernel(const float* __restrict__ A,
                               const float* __restrict__ B,
                               const float* __restrict__ wsrc,
                               const float* __restrict__ wdst) {
    __shared__ uint32_t As[BM * PA];
    __shared__ uint32_t Bs[BK * PB];
    __shared__ float s_ps[BM][2];
    __shared__ float s_pd[BM][2];

    const int tid  = threadIdx.x;
    const int lane = tid & 31;
    const int warp = tid >> 5;
    const int wm   = warp >> 1;
    const int wn   = warp & 1;
    const int row0 = blockIdx.x * BM;
    const int col0 = blockIdx.y * BN;
    const int hd   = blockIdx.y;

    float c[2][4][4];
    #pragma unroll
    for (int mt = 0; mt < 2; mt++)
        #pragma unroll
        for (int nt = 0; nt < 4; nt++)
            #pragma unroll
            for (int r = 0; r < 4; r++) c[mt][nt][r] = 0.f;

    const int ar = tid >> 3;
    const int ac = (tid & 7) * 4;
    const int br = tid >> 4;
    const int bc = (tid & 15) * 4;

    float4 pa[4], pb[2];
    #pragma unroll
    for (int p = 0; p < 4; p++)
        pa[p] = *reinterpret_cast<const float4*>(
            &A[(row0 + ar + p * 32) * Fk + ac]);
    #pragma unroll
    for (int p = 0; p < 2; p++)
        pb[p] = *reinterpret_cast<const float4*>(
            &B[(br + p * 16) * Cc + col0 + bc]);

    const int NTILES = Fk / BK;
    for (int t = 0; t < NTILES; t++) {
        #pragma unroll
        for (int p = 0; p < 4; p++) {
            uint32_t* d = &As[(ar + p * 32) * PA + ac];
            d[0] = f2tf(pa[p].x); d[1] = f2tf(pa[p].y);
            d[2] = f2tf(pa[p].z); d[3] = f2tf(pa[p].w);
        }
        #pragma unroll
        for (int p = 0; p < 2; p++) {
            uint32_t* d = &Bs[(br + p * 16) * PB + bc];
            d[0] = f2tf(pb[p].x); d[1] = f2tf(pb[p].y);
            d[2] = f2tf(pb[p].z); d[3] = f2tf(pb[p].w);
        }
        __syncthreads();

        if (t + 1 < NTILES) {
            int k0 = (t + 1) * BK;
            #pragma unroll
            for (int p = 0; p < 4; p++)
                pa[p] = *reinterpret_cast<const float4*>(
                    &A[(row0 + ar + p * 32) * Fk + k0 + ac]);
            #pragma unroll
            for (int p = 0; p < 2; p++)
                pb[p] = *reinterpret_cast<const float4*>(
                    &B[(k0 + br + p * 16) * Cc + col0 + bc]);
        }

        #pragma unroll
        for (int ks = 0; ks < 4; ks++) {
            const int kk = ks * 8;
            uint32_t af[2][4], bf[4][2];
            #pragma unroll
            for (int mt = 0; mt < 2; mt++) {
                int r = wm * 32 + mt * 16 + (lane >> 2);
                af[mt][0] = As[r * PA + kk + (lane & 3)];
                af[mt][1] = As[(r + 8) * PA + kk + (lane & 3)];
                af[mt][2] = As[r * PA + kk + (lane & 3) + 4];
                af[mt][3] = As[(r + 8) * PA + kk + (lane & 3) + 4];
            }
            #pragma unroll
            for (int nt = 0; nt < 4; nt++) {
                int nc = wn * 32 + nt * 8 + (lane >> 2);
                bf[nt][0] = Bs[(kk + (lane & 3)) * PB + nc];
                bf[nt][1] = Bs[(kk + (lane & 3) + 4) * PB + nc];
            }
            #pragma unroll
            for (int mt = 0; mt < 2; mt++)
                #pragma unroll
                for (int nt = 0; nt < 4; nt++)
                    mma_tf32(c[mt][nt], af[mt], bf[nt]);
        }
        __syncthreads();
    }

    // epilogue 1: write ft accumulators
    #pragma unroll
    for (int mt = 0; mt < 2; mt++) {
        #pragma unroll
        for (int nt = 0; nt < 4; nt++) {
            int r  = row0 + wm * 32 + mt * 16 + (lane >> 2);
            int cc = col0 + wn * 32 + nt * 8 + 2 * (lane & 3);
            *reinterpret_cast<float2*>(&g_ft[r * Cc + cc]) =
                make_float2(c[mt][nt][0], c[mt][nt][1]);
            *reinterpret_cast<float2*>(&g_ft[(r + 8) * Cc + cc]) =
                make_float2(c[mt][nt][2], c[mt][nt][3]);
        }
    }

    // epilogue 2: attention logits for head hd from register accumulators
    float2 ws2[4], wd2[4];
    #pragma unroll
    for (int nt = 0; nt < 4; nt++) {
        int cl = wn * 32 + nt * 8 + 2 * (lane & 3);
        ws2[nt] = *reinterpret_cast<const float2*>(&wsrc[hd * Dd + cl]);
        wd2[nt] = *reinterpret_cast<const float2*>(&wdst[hd * Dd + cl]);
    }
    #pragma unroll
    for (int mt = 0; mt < 2; mt++) {
        float ps0 = 0.f, pd0 = 0.f, ps1 = 0.f, pd1 = 0.f;
        #pragma unroll
        for (int nt = 0; nt < 4; nt++) {
            ps0 += c[mt][nt][0] * ws2[nt].x + c[mt][nt][1] * ws2[nt].y;
            pd0 += c[mt][nt][0] * wd2[nt].x + c[mt][nt][1] * wd2[nt].y;
            ps1 += c[mt][nt][2] * ws2[nt].x + c[mt][nt][3] * ws2[nt].y;
            pd1 += c[mt][nt][2] * wd2[nt].x + c[mt][nt][3] * wd2[nt].y;
        }
        #pragma unroll
        for (int m = 1; m < 4; m <<= 1) {
            ps0 += __shfl_xor_sync(0xffffffffu, ps0, m);
            pd0 += __shfl_xor_sync(0xffffffffu, pd0, m);
            ps1 += __shfl_xor_sync(0xffffffffu, ps1, m);
            pd1 += __shfl_xor_sync(0xffffffffu, pd1, m);
        }
        if ((lane & 3) == 0) {
            int r = wm * 32 + mt * 16 + (lane >> 2);
            s_ps[r][wn]     = ps0;  s_pd[r][wn]     = pd0;
            s_ps[r + 8][wn] = ps1;  s_pd[r + 8][wn] = pd1;
        }
    }
    __syncthreads();
    if (tid < BM) {
        g_esrc[(row0 + tid) * Hh + hd] = s_ps[tid][0] + s_ps[tid][1];
        g_edst[(row0 + tid) * Hh + hd] = s_pd[tid][0] + s_pd[tid][1];
    }
}

// ---------------- CSR build -------------------------------------------------
__global__ void hist_kernel(const int* __restrict__ dst) {
    int base = blockIdx.x * 1024 + threadIdx.x;
    int d0 = dst[base];
    int d1 = dst[base + 256];
    int d2 = dst[base + 512];
    int d3 = dst[base + 768];
    atomicAdd(&g_count[d0], 1);
    atomicAdd(&g_count[d1], 1);
    atomicAdd(&g_count[d2], 1);
    atomicAdd(&g_count[d3], 1);
}

__global__ void scan_kernel() {
    __shared__ int ws[8];
    __shared__ int wo[8];
    __shared__ int s_boff;
    int b = blockIdx.x, t = threadIdx.x, lane = t & 31, w = t >> 5;

    {
        int p = 0;
        for (int i = t; i < b * 256; i += 256) p += g_count[i];
        #pragma unroll
        for (int d = 16; d > 0; d >>= 1) p += __shfl_xor_sync(0xffffffffu, p, d);
        if (lane == 0) ws[w] = p;
        __syncthreads();
        if (t == 0) {
            int s = 0;
            #pragma unroll
            for (int k = 0; k < 8; k++) s += ws[k];
            s_boff = s;
        }
        __syncthreads();
    }

    int i = b * 256 + t;
    int v = g_count[i];
    int x = v;
    #pragma unroll
    for (int d = 1; d < 32; d <<= 1) {
        int y = __shfl_up_sync(0xffffffffu, x, d);
        if (lane >= d) x += y;
    }
    if (lane == 31) ws[w] = x;
    __syncthreads();
    if (t == 0) {
        int a = 0;
        #pragma unroll
        for (int k = 0; k < 8; k++) { wo[k] = a; a += ws[k]; }
    }
    __syncthreads();
    int excl = x - v + wo[w] + s_boff;
    g_off[i] = excl;
    g_cur[i] = excl;
}

__global__ void scatter_kernel(const int* __restrict__ src,
                               const int* __restrict__ dst,
                               const float* __restrict__ dist) {
    int base = blockIdx.x * 1024 + threadIdx.x;
    #pragma unroll
    for (int k = 0; k < 4; k++) {
        int e = base + k * 256;
        int d = dst[e];
        int s = src[e];
        float di = dist[e];
        int p = atomicAdd(&g_cur[d], 1);
        g_srclist[p] = s;
        g_dlist[p]   = di;
    }
}

__global__ void vgather_kernel() {
    int base = blockIdx.x * 1024 + threadIdx.x;
    int s0 = g_srclist[base];
    int s1 = g_srclist[base + 256];
    int s2 = g_srclist[base + 512];
    int s3 = g_srclist[base + 768];
    float4 e0 = *reinterpret_cast<const float4*>(&g_esrc[s0 * Hh]);
    float4 e1 = *reinterpret_cast<const float4*>(&g_esrc[s1 * Hh]);
    float4 e2 = *reinterpret_cast<const float4*>(&g_esrc[s2 * Hh]);
    float4 e3 = *reinterpret_cast<const float4*>(&g_esrc[s3 * Hh]);
    *reinterpret_cast<float4*>(&g_vlist[(base)       * Hh]) = e0;
    *reinterpret_cast<float4*>(&g_vlist[(base + 256) * Hh]) = e1;
    *reinterpret_cast<float4*>(&g_vlist[(base + 512) * Hh]) = e2;
    *reinterpret_cast<float4*>(&g_vlist[(base + 768) * Hh]) = e3;
}

// ---------------- softmax + aggregation: ONE WARP PER NODE ------------------
__device__ __forceinline__ void msum(float& m, float& s, float m2, float s2) {
    float mn = fmaxf(m, m2);
    float a = (s  != 0.f) ? s  * __expf(m  - mn) : 0.f;
    float b = (s2 != 0.f) ? s2 * __expf(m2 - mn) : 0.f;
    m = mn; s = a + b;
}

// 8 warps per block, each warp handles one destination node independently:
// no __syncthreads, no smem. Lane owns 8 output columns (2 x float4).
__global__ void __launch_bounds__(256) agg_kernel(float* __restrict__ out) {
    const int lane = threadIdx.x & 31;
    const int n    = blockIdx.x * 8 + (threadIdx.x >> 5);
    const int off  = g_off[n];
    const int deg  = g_count[n];

    float4 ed4 = *reinterpret_cast<const float4*>(&g_edst[n * Hh]);
    const float edst[Hh] = {ed4.x, ed4.y, ed4.z, ed4.w};

    const float NEGINF = __int_as_float(0xff800000);
    float m[Hh] = {NEGINF, NEGINF, NEGINF, NEGINF};
    float s[Hh] = {0.f, 0.f, 0.f, 0.f};

    // online softmax over this node's edges (coalesced vlist reads)
    for (int i = lane; i < deg; i += 32) {
        float4 es = *reinterpret_cast<const float4*>(&g_vlist[(off + i) * Hh]);
        float ev[Hh] = {es.x, es.y, es.z, es.w};
        #pragma unroll
        for (int h = 0; h < Hh; h++) {
            float v = ev[h] + edst[h];
            v = (v >= 0.f) ? v : NEG * v;
            float mn = fmaxf(m[h], v);
            float a  = (s[h] != 0.f) ? s[h] * __expf(m[h] - mn) : 0.f;
            s[h] = a + __expf(v - mn);
            m[h] = mn;
        }
    }
    #pragma unroll
    for (int d = 16; d > 0; d >>= 1) {
        #pragma unroll
        for (int h = 0; h < Hh; h++) {
            float m2 = __shfl_xor_sync(0xffffffffu, m[h], d);
            float s2 = __shfl_xor_sync(0xffffffffu, s[h], d);
            msum(m[h], s[h], m2, s2);
        }
    }
    float rden[Hh];
    #pragma unroll
    for (int h = 0; h < Hh; h++) rden[h] = (s[h] > 0.f) ? 1.f / s[h] : 0.f;

    // accumulation: lane owns columns [lane*8, lane*8+8)
    const int h = lane >> 3;                 // head of this lane's columns
    const int col = lane * 8;
    float4 acc0 = make_float4(0.f, 0.f, 0.f, 0.f);
    float4 acc1 = make_float4(0.f, 0.f, 0.f, 0.f);

    for (int t0 = 0; t0 < deg; t0 += 32) {
        // lane computes the coefficient for edge t0+lane (all heads)
        int   sI = 0;
        float ax = 0.f, ay = 0.f, az = 0.f, aw = 0.f;
        int i = t0 + lane;
        if (i < deg) {
            int p = off + i;
            sI = g_srclist[p];
            float4 es = *reinterpret_cast<const float4*>(&g_vlist[p * Hh]);
            float di  = g_dlist[p];
            float ev[Hh] = {es.x, es.y, es.z, es.w};
            float av[Hh];
            #pragma unroll
            for (int hh = 0; hh < Hh; hh++) {
                float v = ev[hh] + edst[hh];
                v = (v >= 0.f) ? v : NEG * v;
                av[hh] = __expf(v - m[hh]) * rden[hh] * di;
            }
            ax = av[0]; ay = av[1]; az = av[2]; aw = av[3];
        }
        int cnt = min(32, deg - t0);
        int j = 0;
        // 2x unrolled broadcast loop: both row loads in flight before FMAs
        for (; j + 2 <= cnt; j += 2) {
            int   sj0 = __shfl_sync(0xffffffffu, sI, j);
            int   sj1 = __shfl_sync(0xffffffffu, sI, j + 1);
            float a00 = __shfl_sync(0xffffffffu, ax, j);
            float a01 = __shfl_sync(0xffffffffu, ay, j);
            float a02 = __shfl_sync(0xffffffffu, az, j);
            float a03 = __shfl_sync(0xffffffffu, aw, j);
            float a10 = __shfl_sync(0xffffffffu, ax, j + 1);
            float a11 = __shfl_sync(0xffffffffu, ay, j + 1);
            float a12 = __shfl_sync(0xffffffffu, az, j + 1);
            float a13 = __shfl_sync(0xffffffffu, aw, j + 1);
            float aA  = (h < 2) ? (h ? a01 : a00) : ((h == 2) ? a02 : a03);
            float aB  = (h < 2) ? (h ? a11 : a10) : ((h == 2) ? a12 : a13);
            const float4* frA =
                reinterpret_cast<const float4*>(&g_ft[sj0 * Cc + col]);
            const float4* frB =
                reinterpret_cast<const float4*>(&g_ft[sj1 * Cc + col]);
            float4 fA0 = frA[0];
            float4 fA1 = frA[1];
            float4 fB0 = frB[0];
            float4 fB1 = frB[1];
            acc0.x += fA0.x * aA; acc0.y += fA0.y * aA;
            acc0.z += fA0.z * aA; acc0.w += fA0.w * aA;
            acc1.x += fA1.x * aA; acc1.y += fA1.y * aA;
            acc1.z += fA1.z * aA; acc1.w += fA1.w * aA;
            acc0.x += fB0.x * aB; acc0.y += fB0.y * aB;
            acc0.z += fB0.z * aB; acc0.w += fB0.w * aB;
            acc1.x += fB1.x * aB; acc1.y += fB1.y * aB;
            acc1.z += fB1.z * aB; acc1.w += fB1.w * aB;
        }
        if (j < cnt) {
            int   sj = __shfl_sync(0xffffffffu, sI, j);
            float a0 = __shfl_sync(0xffffffffu, ax, j);
            float a1 = __shfl_sync(0xffffffffu, ay, j);
            float a2 = __shfl_sync(0xffffffffu, az, j);
            float a3 = __shfl_sync(0xffffffffu, aw, j);
            float a  = (h < 2) ? (h ? a1 : a0) : ((h == 2) ? a2 : a3);
            const float4* fr =
                reinterpret_cast<const float4*>(&g_ft[sj * Cc + col]);
            float4 f0 = fr[0];
            float4 f1 = fr[1];
            acc0.x += f0.x * a; acc0.y += f0.y * a;
            acc0.z += f0.z * a; acc0.w += f0.w * a;
            acc1.x += f1.x * a; acc1.y += f1.y * a;
            acc1.z += f1.z * a; acc1.w += f1.w * a;
        }
    }

    float4* po = reinterpret_cast<float4*>(&out[n * Cc + col]);
    po[0] = acc0;
    po[1] = acc1;

    // reset in-degree for next graph replay (hist accumulates)
    if (lane == 0) g_count[n] = 0;
}

// ---------------- launch ----------------------------------------------------
extern "C" void kernel_launch(void* const* d_in, const int* in_sizes, int n_in,
                              void* d_out, int out_size) {
    const float* feat = (const float*)d_in[0];
    const float* dist = (const float*)d_in[1];
    const float* W    = (const float*)d_in[2];
    const float* wsrc = (const float*)d_in[3];
    const float* wdst = (const float*)d_in[4];
    const int*   src  = (const int*)d_in[5];
    const int*   dst  = (const int*)d_in[6];
    float*       out  = (float*)d_out;

    (void)in_sizes; (void)n_in; (void)out_size;

    hist_kernel<<<Ee / 1024, 256>>>(dst);                                   // 0
    scan_kernel<<<125, 256>>>();                                            // 1
    scatter_kernel<<<Ee / 1024, 256>>>(src, dst, dist);                     // 2
    gemm_tc_kernel<<<dim3(Nn / BM, Cc / BN), 256>>>(feat, W, wsrc, wdst);   // 3 (profiled)
    vgather_kernel<<<Ee / 1024, 256>>>();                                   // 4
    agg_kernel<<<Nn / 8, 256>>>(out);                                       // 5
}

// round 16
// speedup vs baseline: 1.9833x; 1.0021x over previous
#include <cuda_runtime.h>
#include <cstdint>

#define Nn 32000
#define Ee 512000
#define Fk 256
#define Hh 4
#define Dd 64
#define Cc 256          // Hh * Dd
#define NEG 0.2f

// ---------------- scratch (device globals: no allocation allowed) ----------
__device__ float g_ft[Nn * Cc];        // projected features [N, 256]
__device__ float g_esrc[Nn * Hh];      // per-node src logits
__device__ float g_edst[Nn * Hh];      // per-node dst logits
__device__ int   g_count[Nn];          // in-degree (zeroed by agg for next replay)
__device__ int   g_off[Nn];            // CSR offsets
__device__ int   g_cur[Nn];            // scatter cursors
__device__ int   g_srclist[Ee];        // src node per CSR slot
__device__ float g_dlist[Ee];          // dist per CSR slot
__device__ float g_vlist[Ee * Hh];     // esrc[src] per CSR slot (4 floats)

// ---------------- tf32 tensor-core GEMM: ft = feat @ W ---------------------
// Round-9 layouts (PA=36/PB=72 conflict-free), now double-buffered:
// one __syncthreads per tile; staging STS overlaps MMAs of previous tile.
// Staging uses STS.128 (uint4) — 6 stores/thread/tile instead of 24.
#define BM 128
#define BN 64
#define BK 32
#define PA 36
#define PB 72

__device__ __forceinline__ uint32_t f2tf(float f) {
    uint32_t o;
    asm("cvt.rna.tf32.f32 %0, %1;" : "=r"(o) : "f"(f));
    return o;
}

__device__ __forceinline__ void mma_tf32(float c[4],
                                         const uint32_t a[4],
                                         const uint32_t b[2]) {
    asm volatile(
        "mma.sync.aligned.m16n8k8.row.col.f32.tf32.tf32.f32 "
        "{%0,%1,%2,%3}, {%4,%5,%6,%7}, {%8,%9}, {%0,%1,%2,%3};"
        : "+f"(c[0]), "+f"(c[1]), "+f"(c[2]), "+f"(c[3])
        : "r"(a[0]), "r"(a[1]), "r"(a[2]), "r"(a[3]),
          "r"(b[0]), "r"(b[1]));
}

__global__ void gemm_tc_kernel(const float* __restrict__ A,
                               const float* __restrict__ B,
                               const float* __restrict__ wsrc,
                               const float* __restrict__ wdst) {
    __shared__ uint32_t As[2][BM * PA];   // 2 x 18432 B
    __shared__ uint32_t Bs[2][BK * PB];   // 2 x  9216 B
    __shared__ float s_ps[BM][2];
    __shared__ float s_pd[BM][2];

    const int tid  = threadIdx.x;
    const int lane = tid & 31;
    const int warp = tid >> 5;
    const int wm   = warp >> 1;
    const int wn   = warp & 1;
    const int row0 = blockIdx.x * BM;
    const int col0 = blockIdx.y * BN;
    const int hd   = blockIdx.y;

    float c[2][4][4];
    #pragma unroll
    for (int mt = 0; mt < 2; mt++)
        #pragma unroll
        for (int nt = 0; nt < 4; nt++)
            #pragma unroll
            for (int r = 0; r < 4; r++) c[mt][nt][r] = 0.f;

    const int ar = tid >> 3;
    const int ac = (tid & 7) * 4;
    const int br = tid >> 4;
    const int bc = (tid & 15) * 4;

    float4 pa[4], pb[2];
    #pragma unroll
    for (int p = 0; p < 4; p++)
        pa[p] = *reinterpret_cast<const float4*>(
            &A[(row0 + ar + p * 32) * Fk + ac]);
    #pragma unroll
    for (int p = 0; p < 2; p++)
        pb[p] = *reinterpret_cast<const float4*>(
            &B[(br + p * 16) * Cc + col0 + bc]);

    // store staged tile (tf32 cvt) into buffer b with STS.128
    auto sts_tile = [&](int b) {
        #pragma unroll
        for (int p = 0; p < 4; p++) {
            uint4 v;
            v.x = f2tf(pa[p].x); v.y = f2tf(pa[p].y);
            v.z = f2tf(pa[p].z); v.w = f2tf(pa[p].w);
            *reinterpret_cast<uint4*>(&As[b][(ar + p * 32) * PA + ac]) = v;
        }
        #pragma unroll
        for (int p = 0; p < 2; p++) {
            uint4 v;
            v.x = f2tf(pb[p].x); v.y = f2tf(pb[p].y);
            v.z = f2tf(pb[p].z); v.w = f2tf(pb[p].w);
            *reinterpret_cast<uint4*>(&Bs[b][(br + p * 16) * PB + bc]) = v;
        }
    };

    sts_tile(0);
    __syncthreads();

    const int NTILES = Fk / BK;        // 8
    for (int t = 0; t < NTILES; t++) {
        const int cb = t & 1;

        // prefetch next tile into registers (overlaps with MMAs below)
        if (t + 1 < NTILES) {
            int k0 = (t + 1) * BK;
            #pragma unroll
            for (int p = 0; p < 4; p++)
                pa[p] = *reinterpret_cast<const float4*>(
                    &A[(row0 + ar + p * 32) * Fk + k0 + ac]);
            #pragma unroll
            for (int p = 0; p < 2; p++)
                pb[p] = *reinterpret_cast<const float4*>(
                    &B[(k0 + br + p * 16) * Cc + col0 + bc]);
        }

        // compute from current buffer
        #pragma unroll
        for (int ks = 0; ks < 4; ks++) {
            const int kk = ks * 8;
            uint32_t af[2][4], bf[4][2];
            #pragma unroll
            for (int mt = 0; mt < 2; mt++) {
                int r = wm * 32 + mt * 16 + (lane >> 2);
                af[mt][0] = As[cb][r * PA + kk + (lane & 3)];
                af[mt][1] = As[cb][(r + 8) * PA + kk + (lane & 3)];
                af[mt][2] = As[cb][r * PA + kk + (lane & 3) + 4];
                af[mt][3] = As[cb][(r + 8) * PA + kk + (lane & 3) + 4];
            }
            #pragma unroll
            for (int nt = 0; nt < 4; nt++) {
                int nc = wn * 32 + nt * 8 + (lane >> 2);
                bf[nt][0] = Bs[cb][(kk + (lane & 3)) * PB + nc];
                bf[nt][1] = Bs[cb][(kk + (lane & 3) + 4) * PB + nc];
            }
            #pragma unroll
            for (int mt = 0; mt < 2; mt++)
                #pragma unroll
                for (int nt = 0; nt < 4; nt++)
                    mma_tf32(c[mt][nt], af[mt], bf[nt]);
        }

        // stage next tile into the other buffer (no readers of it this iter)
        if (t + 1 < NTILES) sts_tile(cb ^ 1);
        __syncthreads();
    }

    // epilogue 1: write ft accumulators
    #pragma unroll
    for (int mt = 0; mt < 2; mt++) {
        #pragma unroll
        for (int nt = 0; nt < 4; nt++) {
            int r  = row0 + wm * 32 + mt * 16 + (lane >> 2);
            int cc = col0 + wn * 32 + nt * 8 + 2 * (lane & 3);
            *reinterpret_cast<float2*>(&g_ft[r * Cc + cc]) =
                make_float2(c[mt][nt][0], c[mt][nt][1]);
            *reinterpret_cast<float2*>(&g_ft[(r + 8) * Cc + cc]) =
                make_float2(c[mt][nt][2], c[mt][nt][3]);
        }
    }

    // epilogue 2: attention logits for head hd from register accumulators
    float2 ws2[4], wd2[4];
    #pragma unroll
    for (int nt = 0; nt < 4; nt++) {
        int cl = wn * 32 + nt * 8 + 2 * (lane & 3);
        ws2[nt] = *reinterpret_cast<const float2*>(&wsrc[hd * Dd + cl]);
        wd2[nt] = *reinterpret_cast<const float2*>(&wdst[hd * Dd + cl]);
    }
    #pragma unroll
    for (int mt = 0; mt < 2; mt++) {
        float ps0 = 0.f, pd0 = 0.f, ps1 = 0.f, pd1 = 0.f;
        #pragma unroll
        for (int nt = 0; nt < 4; nt++) {
            ps0 += c[mt][nt][0] * ws2[nt].x + c[mt][nt][1] * ws2[nt].y;
            pd0 += c[mt][nt][0] * wd2[nt].x + c[mt][nt][1] * wd2[nt].y;
            ps1 += c[mt][nt][2] * ws2[nt].x + c[mt][nt][3] * ws2[nt].y;
            pd1 += c[mt][nt][2] * wd2[nt].x + c[mt][nt][3] * wd2[nt].y;
        }
        #pragma unroll
        for (int m = 1; m < 4; m <<= 1) {
            ps0 += __shfl_xor_sync(0xffffffffu, ps0, m);
            pd0 += __shfl_xor_sync(0xffffffffu, pd0, m);
            ps1 += __shfl_xor_sync(0xffffffffu, ps1, m);
            pd1 += __shfl_xor_sync(0xffffffffu, pd1, m);
        }
        if ((lane & 3) == 0) {
            int r = wm * 32 + mt * 16 + (lane >> 2);
            s_ps[r][wn]     = ps0;  s_pd[r][wn]     = pd0;
            s_ps[r + 8][wn] = ps1;  s_pd[r + 8][wn] = pd1;
        }
    }
    __syncthreads();
    if (tid < BM) {
        g_esrc[(row0 + tid) * Hh + hd] = s_ps[tid][0] + s_ps[tid][1];
        g_edst[(row0 + tid) * Hh + hd] = s_pd[tid][0] + s_pd[tid][1];
    }
}

// ---------------- CSR build -------------------------------------------------
__global__ void hist_kernel(const int* __restrict__ dst) {
    int base = blockIdx.x * 1024 + threadIdx.x;
    int d0 = dst[base];
    int d1 = dst[base + 256];
    int d2 = dst[base + 512];
    int d3 = dst[base + 768];
    atomicAdd(&g_count[d0], 1);
    atomicAdd(&g_count[d1], 1);
    atomicAdd(&g_count[d2], 1);
    atomicAdd(&g_count[d3], 1);
}

__global__ void scan_kernel() {
    __shared__ int ws[8];
    __shared__ int wo[8];
    __shared__ int s_boff;
    int b = blockIdx.x, t = threadIdx.x, lane = t & 31, w = t >> 5;

    {
        int p = 0;
        for (int i = t; i < b * 256; i += 256) p += g_count[i];
        #pragma unroll
        for (int d = 16; d > 0; d >>= 1) p += __shfl_xor_sync(0xffffffffu, p, d);
        if (lane == 0) ws[w] = p;
        __syncthreads();
        if (t == 0) {
            int s = 0;
            #pragma unroll
            for (int k = 0; k < 8; k++) s += ws[k];
            s_boff = s;
        }
        __syncthreads();
    }

    int i = b * 256 + t;
    int v = g_count[i];
    int x = v;
    #pragma unroll
    for (int d = 1; d < 32; d <<= 1) {
        int y = __shfl_up_sync(0xffffffffu, x, d);
        if (lane >= d) x += y;
    }
    if (lane == 31) ws[w] = x;
    __syncthreads();
    if (t == 0) {
        int a = 0;
        #pragma unroll
        for (int k = 0; k < 8; k++) { wo[k] = a; a += ws[k]; }
    }
    __syncthreads();
    int excl = x - v + wo[w] + s_boff;
    g_off[i] = excl;
    g_cur[i] = excl;
}

__global__ void scatter_kernel(const int* __restrict__ src,
                               const int* __restrict__ dst,
                               const float* __restrict__ dist) {
    int base = blockIdx.x * 1024 + threadIdx.x;
    #pragma unroll
    for (int k = 0; k < 4; k++) {
        int e = base + k * 256;
        int d = dst[e];
        int s = src[e];
        float di = dist[e];
        int p = atomicAdd(&g_cur[d], 1);
        g_srclist[p] = s;
        g_dlist[p]   = di;
    }
}

__global__ void vgather_kernel() {
    int base = blockIdx.x * 1024 + threadIdx.x;
    int s0 = g_srclist[base];
    int s1 = g_srclist[base + 256];
    int s2 = g_srclist[base + 512];
    int s3 = g_srclist[base + 768];
    float4 e0 = *reinterpret_cast<const float4*>(&g_esrc[s0 * Hh]);
    float4 e1 = *reinterpret_cast<const float4*>(&g_esrc[s1 * Hh]);
    float4 e2 = *reinterpret_cast<const float4*>(&g_esrc[s2 * Hh]);
    float4 e3 = *reinterpret_cast<const float4*>(&g_esrc[s3 * Hh]);
    *reinterpret_cast<float4*>(&g_vlist[(base)       * Hh]) = e0;
    *reinterpret_cast<float4*>(&g_vlist[(base + 256) * Hh]) = e1;
    *reinterpret_cast<float4*>(&g_vlist[(base + 512) * Hh]) = e2;
    *reinterpret_cast<float4*>(&g_vlist[(base + 768) * Hh]) = e3;
}

// ---------------- softmax + aggregation: ONE WARP PER NODE ------------------
__device__ __forceinline__ void msum(float& m, float& s, float m2, float s2) {
    float mn = fmaxf(m, m2);
    float a = (s  != 0.f) ? s  * __expf(m  - mn) : 0.f;
    float b = (s2 != 0.f) ? s2 * __expf(m2 - mn) : 0.f;
    m = mn; s = a + b;
}

// 8 warps per block, each warp handles one destination node independently:
// no __syncthreads, no smem. Lane owns 8 output columns (2 x float4).
__global__ void __launch_bounds__(256) agg_kernel(float* __restrict__ out) {
    const int lane = threadIdx.x & 31;
    const int n    = blockIdx.x * 8 + (threadIdx.x >> 5);
    const int off  = g_off[n];
    const int deg  = g_count[n];

    float4 ed4 = *reinterpret_cast<const float4*>(&g_edst[n * Hh]);
    const float edst[Hh] = {ed4.x, ed4.y, ed4.z, ed4.w};

    const float NEGINF = __int_as_float(0xff800000);
    float m[Hh] = {NEGINF, NEGINF, NEGINF, NEGINF};
    float s[Hh] = {0.f, 0.f, 0.f, 0.f};

    // online softmax over this node's edges (coalesced vlist reads)
    for (int i = lane; i < deg; i += 32) {
        float4 es = *reinterpret_cast<const float4*>(&g_vlist[(off + i) * Hh]);
        float ev[Hh] = {es.x, es.y, es.z, es.w};
        #pragma unroll
        for (int h = 0; h < Hh; h++) {
            float v = ev[h] + edst[h];
            v = (v >= 0.f) ? v : NEG * v;
            float mn = fmaxf(m[h], v);
            float a  = (s[h] != 0.f) ? s[h] * __expf(m[h] - mn) : 0.f;
            s[h] = a + __expf(v - mn);
            m[h] = mn;
        }
    }
    #pragma unroll
    for (int d = 16; d > 0; d >>= 1) {
        #pragma unroll
        for (int h = 0; h < Hh; h++) {
            float m2 = __shfl_xor_sync(0xffffffffu, m[h], d);
            float s2 = __shfl_xor_sync(0xffffffffu, s[h], d);
            msum(m[h], s[h], m2, s2);
        }
    }
    float rden[Hh];
    #pragma unroll
    for (int h = 0; h < Hh; h++) rden[h] = (s[h] > 0.f) ? 1.f / s[h] : 0.f;

    // accumulation: lane owns columns [lane*8, lane*8+8)
    const int h = lane >> 3;                 // head of this lane's columns
    const int col = lane * 8;
    float4 acc0 = make_float4(0.f, 0.f, 0.f, 0.f);
    float4 acc1 = make_float4(0.f, 0.f, 0.f, 0.f);

    for (int t0 = 0; t0 < deg; t0 += 32) {
        // lane computes the coefficient for edge t0+lane (all heads)
        int   sI = 0;
        float ax = 0.f, ay = 0.f, az = 0.f, aw = 0.f;
        int i = t0 + lane;
        if (i < deg) {
            int p = off + i;
            sI = g_srclist[p];
            float4 es = *reinterpret_cast<const float4*>(&g_vlist[p * Hh]);
            float di  = g_dlist[p];
            float ev[Hh] = {es.x, es.y, es.z, es.w};
            float av[Hh];
            #pragma unroll
            for (int hh = 0; hh < Hh; hh++) {
                float v = ev[hh] + edst[hh];
                v = (v >= 0.f) ? v : NEG * v;
                av[hh] = __expf(v - m[hh]) * rden[hh] * di;
            }
            ax = av[0]; ay = av[1]; az = av[2]; aw = av[3];
        }
        int cnt = min(32, deg - t0);
        int j = 0;
        // 2x unrolled broadcast loop: both row loads in flight before FMAs
        for (; j + 2 <= cnt; j += 2) {
            int   sj0 = __shfl_sync(0xffffffffu, sI, j);
            int   sj1 = __shfl_sync(0xffffffffu, sI, j + 1);
            float a00 = __shfl_sync(0xffffffffu, ax, j);
            float a01 = __shfl_sync(0xffffffffu, ay, j);
            float a02 = __shfl_sync(0xffffffffu, az, j);
            float a03 = __shfl_sync(0xffffffffu, aw, j);
            float a10 = __shfl_sync(0xffffffffu, ax, j + 1);
            float a11 = __shfl_sync(0xffffffffu, ay, j + 1);
            float a12 = __shfl_sync(0xffffffffu, az, j + 1);
            float a13 = __shfl_sync(0xffffffffu, aw, j + 1);
            float aA  = (h < 2) ? (h ? a01 : a00) : ((h == 2) ? a02 : a03);
            float aB  = (h < 2) ? (h ? a11 : a10) : ((h == 2) ? a12 : a13);
            const float4* frA =
                reinterpret_cast<const float4*>(&g_ft[sj0 * Cc + col]);
            const float4* frB =
                reinterpret_cast<const float4*>(&g_ft[sj1 * Cc + col]);
            float4 fA0 = frA[0];
            float4 fA1 = frA[1];
            float4 fB0 = frB[0];
            float4 fB1 = frB[1];
            acc0.x += fA0.x * aA; acc0.y += fA0.y * aA;
            acc0.z += fA0.z * aA; acc0.w += fA0.w * aA;
            acc1.x += fA1.x * aA; acc1.y += fA1.y * aA;
            acc1.z += fA1.z * aA; acc1.w += fA1.w * aA;
            acc0.x += fB0.x * aB; acc0.y += fB0.y * aB;
            acc0.z += fB0.z * aB; acc0.w += fB0.w * aB;
            acc1.x += fB1.x * aB; acc1.y += fB1.y * aB;
            acc1.z += fB1.z * aB; acc1.w += fB1.w * aB;
        }
        if (j < cnt) {
            int   sj = __shfl_sync(0xffffffffu, sI, j);
            float a0 = __shfl_sync(0xffffffffu, ax, j);
            float a1 = __shfl_sync(0xffffffffu, ay, j);
            float a2 = __shfl_sync(0xffffffffu, az, j);
            float a3 = __shfl_sync(0xffffffffu, aw, j);
            float a  = (h < 2) ? (h ? a1 : a0) : ((h == 2) ? a2 : a3);
            const float4* fr =
                reinterpret_cast<const float4*>(&g_ft[sj * Cc + col]);
            float4 f0 = fr[0];
            float4 f1 = fr[1];
            acc0.x += f0.x * a; acc0.y += f0.y * a;
            acc0.z += f0.z * a; acc0.w += f0.w * a;
            acc1.x += f1.x * a; acc1.y += f1.y * a;
            acc1.z += f1.z * a; acc1.w += f1.w * a;
        }
    }

    float4* po = reinterpret_cast<float4*>(&out[n * Cc + col]);
    po[0] = acc0;
    po[1] = acc1;

    // reset in-degree for next graph replay (hist accumulates)
    if (lane == 0) g_count[n] = 0;
}

// ---------------- launch ----------------------------------------------------
extern "C" void kernel_launch(void* const* d_in, const int* in_sizes, int n_in,
                              void* d_out, int out_size) {
    const float* feat = (const float*)d_in[0];
    const float* dist = (const float*)d_in[1];
    const float* W    = (const float*)d_in[2];
    const float* wsrc = (const float*)d_in[3];
    const float* wdst = (const float*)d_in[4];
    const int*   src  = (const int*)d_in[5];
    const int*   dst  = (const int*)d_in[6];
    float*       out  = (float*)d_out;

    (void)in_sizes; (void)n_in; (void)out_size;

    hist_kernel<<<Ee / 1024, 256>>>(dst);                                   // 0
    scan_kernel<<<125, 256>>>();                                            // 1
    scatter_kernel<<<Ee / 1024, 256>>>(src, dst, dist);                     // 2
    gemm_tc_kernel<<<dim3(Nn / BM, Cc / BN), 256>>>(feat, W, wsrc, wdst);   // 3 (profiled)
    vgather_kernel<<<Ee / 1024, 256>>>();                                   // 4
    agg_kernel<<<Nn / 8, 256>>>(out);                                       // 5
}